// round 12
// baseline (speedup 1.0000x reference)
#include <cuda_runtime.h>

#define N_HID     128
#define N_ETYPES  10
#define N_EDGES   100000
#define TOTAL_EDGES (N_ETYPES * N_EDGES)
#define EPW       8   // edges per warp (2 groups of 4)

// Octet layout: 8 lanes per edge, lane j=lane&7 owns a 16B slice of each 128B
// chunk; octet o=lane>>3 owns one edge of the group. Dot products use 4
// independent per-chunk FMA chains (depth ~24 cyc vs 64 for a single chain)
// so the warp returns to its next load batch sooner -> higher L1 duty cycle.
__global__ void __launch_bounds__(128, 9) distmult_kernel(
    const float* __restrict__ h,
    const float* __restrict__ W,
    const int* __restrict__ src,
    const int* __restrict__ dst,
    const int* __restrict__ rel,
    float* __restrict__ out)
{
    const int warp = (blockIdx.x * blockDim.x + threadIdx.x) >> 5;
    const int lane = threadIdx.x & 31;
    const int e0 = warp * EPW;
    if (e0 >= TOTAL_EDGES) return;

    const int j = lane & 7;        // 16B slice within chunk
    const int o = lane >> 3;       // edge within group

    const int t = e0 / N_EDGES;    // 100000 % 8 == 0: no etype straddle
    const int r = __ldg(&rel[t]);
    const float* wrow = W + r * N_HID;

    const float4 w0 = __ldg((const float4*)(wrow +  0) + j);
    const float4 w1 = __ldg((const float4*)(wrow + 32) + j);
    const float4 w2 = __ldg((const float4*)(wrow + 64) + j);
    const float4 w3 = __ldg((const float4*)(wrow + 96) + j);

    float acc0, acc1;

#define GROUP(accv, gbase)                                                     \
    {                                                                          \
        const int s = __ldg(src + (gbase) + o);                                \
        const int d = __ldg(dst + (gbase) + o);                                \
        const float* sa = h + (size_t)s * N_HID;                               \
        const float* sb = h + (size_t)d * N_HID;                               \
        /* 8 independent gathers: 4 chunks x {src,dst} */                      \
        const float4 a0 = __ldg((const float4*)(sa +  0) + j);                 \
        const float4 a1 = __ldg((const float4*)(sa + 32) + j);                 \
        const float4 a2 = __ldg((const float4*)(sa + 64) + j);                 \
        const float4 a3 = __ldg((const float4*)(sa + 96) + j);                 \
        const float4 b0 = __ldg((const float4*)(sb +  0) + j);                 \
        const float4 b1 = __ldg((const float4*)(sb + 32) + j);                 \
        const float4 b2 = __ldg((const float4*)(sb + 64) + j);                 \
        const float4 b3 = __ldg((const float4*)(sb + 96) + j);                 \
        /* 4 independent per-chunk chains, then pairwise combine */            \
        float p0 = a0.x * w0.x * b0.x;                                         \
        p0 = fmaf(a0.y * w0.y, b0.y, p0);                                      \
        p0 = fmaf(a0.z * w0.z, b0.z, p0);                                      \
        p0 = fmaf(a0.w * w0.w, b0.w, p0);                                      \
        float p1 = a1.x * w1.x * b1.x;                                         \
        p1 = fmaf(a1.y * w1.y, b1.y, p1);                                      \
        p1 = fmaf(a1.z * w1.z, b1.z, p1);                                      \
        p1 = fmaf(a1.w * w1.w, b1.w, p1);                                      \
        float p2 = a2.x * w2.x * b2.x;                                         \
        p2 = fmaf(a2.y * w2.y, b2.y, p2);                                      \
        p2 = fmaf(a2.z * w2.z, b2.z, p2);                                      \
        p2 = fmaf(a2.w * w2.w, b2.w, p2);                                      \
        float p3 = a3.x * w3.x * b3.x;                                         \
        p3 = fmaf(a3.y * w3.y, b3.y, p3);                                      \
        p3 = fmaf(a3.z * w3.z, b3.z, p3);                                      \
        p3 = fmaf(a3.w * w3.w, b3.w, p3);                                      \
        accv = (p0 + p1) + (p2 + p3);                                          \
    }

    GROUP(acc0, e0)        // edges e0   .. e0+3  (octet o -> edge e0+o)
    GROUP(acc1, e0 + 4)    // edges e0+4 .. e0+7
#undef GROUP

    // Reduce within octet (8 lanes) for both groups: 4 SHFL + 1 mux.
    acc0 += __shfl_xor_sync(0xffffffffu, acc0, 4);
    acc1 += __shfl_xor_sync(0xffffffffu, acc1, 4);
    float m = (lane & 4) ? acc1 : acc0;    // bit2 selects group
    m += __shfl_xor_sync(0xffffffffu, m, 2);
    m += __shfl_xor_sync(0xffffffffu, m, 1);
    // lane l: octet o = l>>3 , group g = (l>>2)&1 -> edge e0 + 4g + o

    if ((lane & 3) == 0) {
        const int g = (lane >> 2) & 1;
        const float sig = 1.0f / (1.0f + __expf(-m));   // MUFU only on storing lanes
        out[e0 + 4 * g + o] = sig;   // 8 floats within one 32B span
    }
}

extern "C" void kernel_launch(void* const* d_in, const int* in_sizes, int n_in,
                              void* d_out, int out_size)
{
    const float* h   = (const float*)d_in[0];   // [N_NODES, 128]
    const float* W   = (const float*)d_in[1];   // [10, 128]
    const int*   src = (const int*)d_in[2];     // [10, 100000] int32
    const int*   dst = (const int*)d_in[3];     // [10, 100000] int32
    const int*   rel = (const int*)d_in[4];     // [10] int32
    float* out = (float*)d_out;                 // [10, 100000]

    const int threads = 128;                     // 4 warps/block, 32 edges/block
    const int warps_needed = TOTAL_EDGES / EPW;  // 125000
    const int blocks = (warps_needed * 32 + threads - 1) / threads;  // 31250
    distmult_kernel<<<blocks, threads>>>(h, W, src, dst, rel, out);
}